// round 1
// baseline (speedup 1.0000x reference)
#include <cuda_runtime.h>
#include <math_constants.h>

#define HID   64
#define MAXN  50000

// Per-node precomputed tables, stride 8 floats for float4 alignment.
// srcTab[n*8 + 0..3] = ps (x0·Wsp + bsp), [n*8+4] = gs (x·Wsg + bsg)
// dstTab[n*8 + 0..3] = pd (x0·Wdp),       [n*8+4] = gd (x·Wdg + bdg)
__device__ float g_srcTab[MAXN * 8];
__device__ float g_dstTab[MAXN * 8];

__global__ void zero_kernel(float* __restrict__ out, int n) {
    int i = blockIdx.x * blockDim.x + threadIdx.x;
    if (i < n) out[i] = 0.0f;
}

// 8 lanes per node; lane handles elements [sub*4 .. sub*4+3] and [32+sub*4 ..].
__global__ void node_kernel(const float* __restrict__ x,
                            const float* __restrict__ x0,
                            const float* __restrict__ Wsg, const float* __restrict__ bsg,
                            const float* __restrict__ Wdg, const float* __restrict__ bdg,
                            const float* __restrict__ Wsp, const float* __restrict__ bsp,
                            const float* __restrict__ Wdp,
                            int n)
{
    int t    = blockIdx.x * blockDim.x + threadIdx.x;
    int node = t >> 3;
    int sub  = t & 7;
    if (node >= n) return;

    const size_t base = (size_t)node * HID;
    const int h0 = sub * 4;        // first element of chunk A
    const int h1 = 32 + sub * 4;   // first element of chunk B

    float4 xa  = *(const float4*)(x  + base + h0);
    float4 xb  = *(const float4*)(x  + base + h1);
    float4 x0a = *(const float4*)(x0 + base + h0);
    float4 x0b = *(const float4*)(x0 + base + h1);

    float gs = 0.f, gd = 0.f;
    float ps0 = 0.f, ps1 = 0.f, ps2 = 0.f, ps3 = 0.f;
    float pd0 = 0.f, pd1 = 0.f, pd2 = 0.f, pd3 = 0.f;

    const float* xav  = (const float*)&xa;
    const float* xbv  = (const float*)&xb;
    const float* x0av = (const float*)&x0a;
    const float* x0bv = (const float*)&x0b;

#pragma unroll
    for (int k = 0; k < 4; k++) {
        int ha = h0 + k, hb = h1 + k;
        gs += xav[k] * __ldg(Wsg + ha) + xbv[k] * __ldg(Wsg + hb);
        gd += xav[k] * __ldg(Wdg + ha) + xbv[k] * __ldg(Wdg + hb);
        float4 wsa = *(const float4*)(Wsp + ha * 4);
        float4 wsb = *(const float4*)(Wsp + hb * 4);
        float4 wda = *(const float4*)(Wdp + ha * 4);
        float4 wdb = *(const float4*)(Wdp + hb * 4);
        ps0 += x0av[k] * wsa.x + x0bv[k] * wsb.x;
        ps1 += x0av[k] * wsa.y + x0bv[k] * wsb.y;
        ps2 += x0av[k] * wsa.z + x0bv[k] * wsb.z;
        ps3 += x0av[k] * wsa.w + x0bv[k] * wsb.w;
        pd0 += x0av[k] * wda.x + x0bv[k] * wdb.x;
        pd1 += x0av[k] * wda.y + x0bv[k] * wdb.y;
        pd2 += x0av[k] * wda.z + x0bv[k] * wdb.z;
        pd3 += x0av[k] * wda.w + x0bv[k] * wdb.w;
    }

    // reduce across the 8 lanes of this node
#pragma unroll
    for (int off = 4; off >= 1; off >>= 1) {
        gs  += __shfl_xor_sync(0xffffffffu, gs,  off);
        gd  += __shfl_xor_sync(0xffffffffu, gd,  off);
        ps0 += __shfl_xor_sync(0xffffffffu, ps0, off);
        ps1 += __shfl_xor_sync(0xffffffffu, ps1, off);
        ps2 += __shfl_xor_sync(0xffffffffu, ps2, off);
        ps3 += __shfl_xor_sync(0xffffffffu, ps3, off);
        pd0 += __shfl_xor_sync(0xffffffffu, pd0, off);
        pd1 += __shfl_xor_sync(0xffffffffu, pd1, off);
        pd2 += __shfl_xor_sync(0xffffffffu, pd2, off);
        pd3 += __shfl_xor_sync(0xffffffffu, pd3, off);
    }

    if (sub == 0) {
        float4 psv = make_float4(ps0 + __ldg(bsp + 0), ps1 + __ldg(bsp + 1),
                                 ps2 + __ldg(bsp + 2), ps3 + __ldg(bsp + 3));
        float4 pdv = make_float4(pd0, pd1, pd2, pd3);
        *(float4*)(g_srcTab + (size_t)node * 8) = psv;
        g_srcTab[(size_t)node * 8 + 4] = gs + __ldg(bsg);
        *(float4*)(g_dstTab + (size_t)node * 8) = pdv;
        g_dstTab[(size_t)node * 8 + 4] = gd + __ldg(bdg);
    }
}

// 16 lanes per edge. Early-exit on cutoff==0 (r > 4.0) BEFORE touching y.
__global__ void edge_kernel(const float* __restrict__ y,
                            const float* __restrict__ bondlength,
                            const int* __restrict__ src,
                            const int* __restrict__ dst,
                            const float* __restrict__ Weg,
                            const float* __restrict__ beg,
                            float* __restrict__ atom,
                            int E)
{
    __shared__ float sWeg[HID];
    int tid = threadIdx.x;
    if (tid < HID) sWeg[tid] = Weg[tid];
    __syncthreads();

    int gt  = blockIdx.x * blockDim.x + tid;
    int e   = gt >> 4;
    int sub = gt & 15;
    if (e >= E) return;

    float r = __ldg(bondlength + e);
    if (r > 4.0f) return;   // cutoff == 0: zero contribution, skip y load + atomic

    float4 yv = *(const float4*)(y + (size_t)e * HID + sub * 4);
    float4 wv = *(const float4*)(sWeg + sub * 4);
    float d = yv.x * wv.x + yv.y * wv.y + yv.z * wv.z + yv.w * wv.w;

#pragma unroll
    for (int off = 8; off >= 1; off >>= 1)
        d += __shfl_xor_sync(0xffffffffu, d, off);

    if (sub == 0) {
        int s  = src[e];
        int dn = dst[e];
        float4 ps = *(const float4*)(g_srcTab + (size_t)s * 8);
        float  gs = g_srcTab[(size_t)s * 8 + 4];
        float4 pd = *(const float4*)(g_dstTab + (size_t)dn * 8);
        float  gd = g_dstTab[(size_t)dn * 8 + 4];

        float m  = gs + gd + d + __ldg(beg);
        float bo = 1.0f / (1.0f + expf(-m));

        float p0 = expf(ps.x + pd.x);
        float p1 = expf(ps.y + pd.y);
        float p2 = expf(ps.z + pd.z);
        float p3 = expf(ps.w + pd.w);

        float frep = p0 * expf(-p1 * r);
        float fatt = p2 * expf(-p3 * r);

        // cutoff: 1 for r < 3.8; 0.5 - 0.5*sin(pi*(r-3.9)/0.2) for 3.8 <= r <= 4.0
        float c = 1.0f;
        if (r >= 3.8f)
            c = 0.5f - 0.5f * sinf(CUDART_PI_F * (r - 3.9f) * 5.0f);

        float V = c * (frep - bo * fatt);
        atomicAdd(atom + dn, V);
    }
}

__global__ void reduce_mean_kernel(const float* __restrict__ atom,
                                   float* __restrict__ out0, int n)
{
    __shared__ float smem[256];
    float acc = 0.f;
    for (int i = blockIdx.x * blockDim.x + threadIdx.x; i < n;
         i += gridDim.x * blockDim.x)
        acc += atom[i];
#pragma unroll
    for (int off = 16; off >= 1; off >>= 1)
        acc += __shfl_xor_sync(0xffffffffu, acc, off);
    if ((threadIdx.x & 31) == 0) smem[threadIdx.x >> 5] = acc;
    __syncthreads();
    if (threadIdx.x == 0) {
        float s = 0.f;
        int nw = blockDim.x >> 5;
        for (int w = 0; w < nw; w++) s += smem[w];
        atomicAdd(out0, s / (float)n);
    }
}

extern "C" void kernel_launch(void* const* d_in, const int* in_sizes, int n_in,
                              void* d_out, int out_size)
{
    const float* x    = (const float*)d_in[0];
    const float* x0   = (const float*)d_in[1];
    const float* y    = (const float*)d_in[2];
    const float* bond = (const float*)d_in[3];
    const int*   src  = (const int*)d_in[4];
    const int*   dst  = (const int*)d_in[5];
    const float* Wsg  = (const float*)d_in[6];
    const float* bsg  = (const float*)d_in[7];
    const float* Wdg  = (const float*)d_in[8];
    const float* bdg  = (const float*)d_in[9];
    const float* Weg  = (const float*)d_in[10];
    const float* beg  = (const float*)d_in[11];
    const float* Wsp  = (const float*)d_in[12];
    const float* bsp  = (const float*)d_in[13];
    const float* Wdp  = (const float*)d_in[14];

    const int N = in_sizes[0] / HID;   // 50000
    const int E = in_sizes[3];         // 1600000

    float* out = (float*)d_out;        // out[0] = energy, out[1..N] = atomwise

    // 1) zero the full output (energy accumulator + atomwise accumulators)
    zero_kernel<<<(out_size + 255) / 256, 256>>>(out, out_size);

    // 2) per-node gate/param precompute (8 lanes/node)
    node_kernel<<<(N * 8 + 255) / 256, 256>>>(x, x0, Wsg, bsg, Wdg, bdg,
                                              Wsp, bsp, Wdp, N);

    // 3) per-edge: gated sigmoid + pair potential + scatter-add (16 lanes/edge)
    long long ethreads = (long long)E * 16;
    edge_kernel<<<(int)((ethreads + 255) / 256), 256>>>(y, bond, src, dst,
                                                        Weg, beg, out + 1, E);

    // 4) mean over atomwise energies -> out[0]
    reduce_mean_kernel<<<64, 256>>>(out + 1, out, N);
}

// round 2
// speedup vs baseline: 1.6873x; 1.6873x over previous
#include <cuda_runtime.h>
#include <math_constants.h>

#define HID   64
#define MAXN  50000

// Per-node precomputed tables, stride 8 floats for float4 alignment.
// srcTab[n*8 + 0..3] = ps (x0·Wsp + bsp), [n*8+4] = gs (x·Wsg + bsg)
// dstTab[n*8 + 0..3] = pd (x0·Wdp),       [n*8+4] = gd (x·Wdg + bdg)
__device__ float g_srcTab[MAXN * 8];
__device__ float g_dstTab[MAXN * 8];

__global__ void zero_kernel(float* __restrict__ out, int n) {
    int i = blockIdx.x * blockDim.x + threadIdx.x;
    if (i < n) out[i] = 0.0f;
}

// 8 lanes per node; lane handles elements [sub*4 .. sub*4+3] and [32+sub*4 ..].
__global__ void node_kernel(const float* __restrict__ x,
                            const float* __restrict__ x0,
                            const float* __restrict__ Wsg, const float* __restrict__ bsg,
                            const float* __restrict__ Wdg, const float* __restrict__ bdg,
                            const float* __restrict__ Wsp, const float* __restrict__ bsp,
                            const float* __restrict__ Wdp,
                            int n)
{
    int t    = blockIdx.x * blockDim.x + threadIdx.x;
    int node = t >> 3;
    int sub  = t & 7;
    if (node >= n) return;

    const size_t base = (size_t)node * HID;
    const int h0 = sub * 4;        // first element of chunk A
    const int h1 = 32 + sub * 4;   // first element of chunk B

    float4 xa  = *(const float4*)(x  + base + h0);
    float4 xb  = *(const float4*)(x  + base + h1);
    float4 x0a = *(const float4*)(x0 + base + h0);
    float4 x0b = *(const float4*)(x0 + base + h1);

    float gs = 0.f, gd = 0.f;
    float ps0 = 0.f, ps1 = 0.f, ps2 = 0.f, ps3 = 0.f;
    float pd0 = 0.f, pd1 = 0.f, pd2 = 0.f, pd3 = 0.f;

    const float* xav  = (const float*)&xa;
    const float* xbv  = (const float*)&xb;
    const float* x0av = (const float*)&x0a;
    const float* x0bv = (const float*)&x0b;

#pragma unroll
    for (int k = 0; k < 4; k++) {
        int ha = h0 + k, hb = h1 + k;
        gs += xav[k] * __ldg(Wsg + ha) + xbv[k] * __ldg(Wsg + hb);
        gd += xav[k] * __ldg(Wdg + ha) + xbv[k] * __ldg(Wdg + hb);
        float4 wsa = *(const float4*)(Wsp + ha * 4);
        float4 wsb = *(const float4*)(Wsp + hb * 4);
        float4 wda = *(const float4*)(Wdp + ha * 4);
        float4 wdb = *(const float4*)(Wdp + hb * 4);
        ps0 += x0av[k] * wsa.x + x0bv[k] * wsb.x;
        ps1 += x0av[k] * wsa.y + x0bv[k] * wsb.y;
        ps2 += x0av[k] * wsa.z + x0bv[k] * wsb.z;
        ps3 += x0av[k] * wsa.w + x0bv[k] * wsb.w;
        pd0 += x0av[k] * wda.x + x0bv[k] * wdb.x;
        pd1 += x0av[k] * wda.y + x0bv[k] * wdb.y;
        pd2 += x0av[k] * wda.z + x0bv[k] * wdb.z;
        pd3 += x0av[k] * wda.w + x0bv[k] * wdb.w;
    }

    // reduce across the 8 lanes of this node
#pragma unroll
    for (int off = 4; off >= 1; off >>= 1) {
        gs  += __shfl_xor_sync(0xffffffffu, gs,  off);
        gd  += __shfl_xor_sync(0xffffffffu, gd,  off);
        ps0 += __shfl_xor_sync(0xffffffffu, ps0, off);
        ps1 += __shfl_xor_sync(0xffffffffu, ps1, off);
        ps2 += __shfl_xor_sync(0xffffffffu, ps2, off);
        ps3 += __shfl_xor_sync(0xffffffffu, ps3, off);
        pd0 += __shfl_xor_sync(0xffffffffu, pd0, off);
        pd1 += __shfl_xor_sync(0xffffffffu, pd1, off);
        pd2 += __shfl_xor_sync(0xffffffffu, pd2, off);
        pd3 += __shfl_xor_sync(0xffffffffu, pd3, off);
    }

    if (sub == 0) {
        float4 psv = make_float4(ps0 + __ldg(bsp + 0), ps1 + __ldg(bsp + 1),
                                 ps2 + __ldg(bsp + 2), ps3 + __ldg(bsp + 3));
        float4 pdv = make_float4(pd0, pd1, pd2, pd3);
        *(float4*)(g_srcTab + (size_t)node * 8) = psv;
        g_srcTab[(size_t)node * 8 + 4] = gs + __ldg(bsg);
        *(float4*)(g_dstTab + (size_t)node * 8) = pdv;
        g_dstTab[(size_t)node * 8 + 4] = gd + __ldg(bdg);
    }
}

// 8 lanes per edge. Predicated (no early return) so loads can issue with MLP,
// all lanes stay alive for the shuffle reduction, and the cutoff still skips
// the 256B y-row read for dead edges.
__global__ void edge_kernel(const float* __restrict__ y,
                            const float* __restrict__ bondlength,
                            const int* __restrict__ src,
                            const int* __restrict__ dst,
                            const float* __restrict__ Weg,
                            const float* __restrict__ beg,
                            float* __restrict__ atom,
                            int E)
{
    __shared__ float sWeg[HID];
    int tid = threadIdx.x;
    if (tid < HID) sWeg[tid] = Weg[tid];
    __syncthreads();

    int gt  = blockIdx.x * blockDim.x + tid;
    int e   = gt >> 3;
    int sub = gt & 7;

    bool inrange = (e < E);
    float r = inrange ? __ldg(bondlength + e) : 5.0f;
    bool act = inrange && (r <= 4.0f);

    float d = 0.0f;
    if (act) {
        const float* yp = y + (size_t)e * HID + sub * 8;
        float4 a = *(const float4*)(yp);
        float4 b = *(const float4*)(yp + 4);       // independent: MLP 2
        float4 wa = *(const float4*)(sWeg + sub * 8);
        float4 wb = *(const float4*)(sWeg + sub * 8 + 4);
        d = a.x * wa.x + a.y * wa.y + a.z * wa.z + a.w * wa.w
          + b.x * wb.x + b.y * wb.y + b.z * wb.z + b.w * wb.w;
    }

    // reduce within the 8-lane group (xor offsets < 8 stay inside the group)
    d += __shfl_xor_sync(0xffffffffu, d, 4);
    d += __shfl_xor_sync(0xffffffffu, d, 2);
    d += __shfl_xor_sync(0xffffffffu, d, 1);

    if (act && sub == 0) {
        int s  = src[e];
        int dn = dst[e];
        float4 ps = *(const float4*)(g_srcTab + (size_t)s * 8);
        float  gs = g_srcTab[(size_t)s * 8 + 4];
        float4 pd = *(const float4*)(g_dstTab + (size_t)dn * 8);
        float  gd = g_dstTab[(size_t)dn * 8 + 4];

        float m  = gs + gd + d + __ldg(beg);
        float bo = 1.0f / (1.0f + __expf(-m));

        float p0 = __expf(ps.x + pd.x);
        float p1 = __expf(ps.y + pd.y);
        float p2 = __expf(ps.z + pd.z);
        float p3 = __expf(ps.w + pd.w);

        float frep = p0 * __expf(-p1 * r);
        float fatt = p2 * __expf(-p3 * r);

        // cutoff: 1 for r < 3.8; 0.5 - 0.5*sin(pi*(r-3.9)/0.2) for 3.8 <= r <= 4.0
        float c = 1.0f;
        if (r >= 3.8f)
            c = 0.5f - 0.5f * __sinf(CUDART_PI_F * (r - 3.9f) * 5.0f);

        float V = c * (frep - bo * fatt);
        atomicAdd(atom + dn, V);
    }
}

__global__ void reduce_mean_kernel(const float* __restrict__ atom,
                                   float* __restrict__ out0, int n)
{
    __shared__ float smem[256];
    float acc = 0.f;
    for (int i = blockIdx.x * blockDim.x + threadIdx.x; i < n;
         i += gridDim.x * blockDim.x)
        acc += atom[i];
#pragma unroll
    for (int off = 16; off >= 1; off >>= 1)
        acc += __shfl_xor_sync(0xffffffffu, acc, off);
    if ((threadIdx.x & 31) == 0) smem[threadIdx.x >> 5] = acc;
    __syncthreads();
    if (threadIdx.x == 0) {
        float s = 0.f;
        int nw = blockDim.x >> 5;
        for (int w = 0; w < nw; w++) s += smem[w];
        atomicAdd(out0, s / (float)n);
    }
}

extern "C" void kernel_launch(void* const* d_in, const int* in_sizes, int n_in,
                              void* d_out, int out_size)
{
    const float* x    = (const float*)d_in[0];
    const float* x0   = (const float*)d_in[1];
    const float* y    = (const float*)d_in[2];
    const float* bond = (const float*)d_in[3];
    const int*   src  = (const int*)d_in[4];
    const int*   dst  = (const int*)d_in[5];
    const float* Wsg  = (const float*)d_in[6];
    const float* bsg  = (const float*)d_in[7];
    const float* Wdg  = (const float*)d_in[8];
    const float* bdg  = (const float*)d_in[9];
    const float* Weg  = (const float*)d_in[10];
    const float* beg  = (const float*)d_in[11];
    const float* Wsp  = (const float*)d_in[12];
    const float* bsp  = (const float*)d_in[13];
    const float* Wdp  = (const float*)d_in[14];

    const int N = in_sizes[0] / HID;   // 50000
    const int E = in_sizes[3];         // 1600000

    float* out = (float*)d_out;        // out[0] = energy, out[1..N] = atomwise

    // 1) zero the full output (energy accumulator + atomwise accumulators)
    zero_kernel<<<(out_size + 255) / 256, 256>>>(out, out_size);

    // 2) per-node gate/param precompute (8 lanes/node)
    node_kernel<<<(N * 8 + 255) / 256, 256>>>(x, x0, Wsg, bsg, Wdg, bdg,
                                              Wsp, bsp, Wdp, N);

    // 3) per-edge: gated sigmoid + pair potential + scatter-add (8 lanes/edge)
    long long ethreads = (long long)E * 8;
    edge_kernel<<<(int)((ethreads + 255) / 256), 256>>>(y, bond, src, dst,
                                                        Weg, beg, out + 1, E);

    // 4) mean over atomwise energies -> out[0]
    reduce_mean_kernel<<<64, 256>>>(out + 1, out, N);
}

// round 4
// speedup vs baseline: 2.1806x; 1.2923x over previous
#include <cuda_runtime.h>
#include <math_constants.h>

#define HID   64
#define MAXN  50000

// Per-node precomputed tables, stride 8 floats for float4 alignment.
// srcTab[n*8 + 0..3] = ps (x0·Wsp + bsp), [n*8+4] = gs (x·Wsg + bsg)
// dstTab[n*8 + 0..3] = pd (x0·Wdp),       [n*8+4] = gd (x·Wdg + bdg)
__device__ float g_srcTab[MAXN * 8];
__device__ float g_dstTab[MAXN * 8];

__global__ void zero_kernel(float* __restrict__ out, int n) {
    int i = blockIdx.x * blockDim.x + threadIdx.x;
    if (i < n) out[i] = 0.0f;
}

// 8 lanes per node; lane handles elements [sub*4 .. sub*4+3] and [32+sub*4 ..].
__global__ void node_kernel(const float* __restrict__ x,
                            const float* __restrict__ x0,
                            const float* __restrict__ Wsg, const float* __restrict__ bsg,
                            const float* __restrict__ Wdg, const float* __restrict__ bdg,
                            const float* __restrict__ Wsp, const float* __restrict__ bsp,
                            const float* __restrict__ Wdp,
                            int n)
{
    int t    = blockIdx.x * blockDim.x + threadIdx.x;
    int node = t >> 3;
    int sub  = t & 7;
    if (node >= n) return;

    const size_t base = (size_t)node * HID;
    const int h0 = sub * 4;        // first element of chunk A
    const int h1 = 32 + sub * 4;   // first element of chunk B

    float4 xa  = *(const float4*)(x  + base + h0);
    float4 xb  = *(const float4*)(x  + base + h1);
    float4 x0a = *(const float4*)(x0 + base + h0);
    float4 x0b = *(const float4*)(x0 + base + h1);

    float gs = 0.f, gd = 0.f;
    float ps0 = 0.f, ps1 = 0.f, ps2 = 0.f, ps3 = 0.f;
    float pd0 = 0.f, pd1 = 0.f, pd2 = 0.f, pd3 = 0.f;

    const float* xav  = (const float*)&xa;
    const float* xbv  = (const float*)&xb;
    const float* x0av = (const float*)&x0a;
    const float* x0bv = (const float*)&x0b;

#pragma unroll
    for (int k = 0; k < 4; k++) {
        int ha = h0 + k, hb = h1 + k;
        gs += xav[k] * __ldg(Wsg + ha) + xbv[k] * __ldg(Wsg + hb);
        gd += xav[k] * __ldg(Wdg + ha) + xbv[k] * __ldg(Wdg + hb);
        float4 wsa = *(const float4*)(Wsp + ha * 4);
        float4 wsb = *(const float4*)(Wsp + hb * 4);
        float4 wda = *(const float4*)(Wdp + ha * 4);
        float4 wdb = *(const float4*)(Wdp + hb * 4);
        ps0 += x0av[k] * wsa.x + x0bv[k] * wsb.x;
        ps1 += x0av[k] * wsa.y + x0bv[k] * wsb.y;
        ps2 += x0av[k] * wsa.z + x0bv[k] * wsb.z;
        ps3 += x0av[k] * wsa.w + x0bv[k] * wsb.w;
        pd0 += x0av[k] * wda.x + x0bv[k] * wdb.x;
        pd1 += x0av[k] * wda.y + x0bv[k] * wdb.y;
        pd2 += x0av[k] * wda.z + x0bv[k] * wdb.z;
        pd3 += x0av[k] * wda.w + x0bv[k] * wdb.w;
    }

    // reduce across the 8 lanes of this node
#pragma unroll
    for (int off = 4; off >= 1; off >>= 1) {
        gs  += __shfl_xor_sync(0xffffffffu, gs,  off);
        gd  += __shfl_xor_sync(0xffffffffu, gd,  off);
        ps0 += __shfl_xor_sync(0xffffffffu, ps0, off);
        ps1 += __shfl_xor_sync(0xffffffffu, ps1, off);
        ps2 += __shfl_xor_sync(0xffffffffu, ps2, off);
        ps3 += __shfl_xor_sync(0xffffffffu, ps3, off);
        pd0 += __shfl_xor_sync(0xffffffffu, pd0, off);
        pd1 += __shfl_xor_sync(0xffffffffu, pd1, off);
        pd2 += __shfl_xor_sync(0xffffffffu, pd2, off);
        pd3 += __shfl_xor_sync(0xffffffffu, pd3, off);
    }

    if (sub == 0) {
        float4 psv = make_float4(ps0 + __ldg(bsp + 0), ps1 + __ldg(bsp + 1),
                                 ps2 + __ldg(bsp + 2), ps3 + __ldg(bsp + 3));
        float4 pdv = make_float4(pd0, pd1, pd2, pd3);
        *(float4*)(g_srcTab + (size_t)node * 8) = psv;
        g_srcTab[(size_t)node * 8 + 4] = gs + __ldg(bsg);
        *(float4*)(g_dstTab + (size_t)node * 8) = pdv;
        g_dstTab[(size_t)node * 8 + 4] = gd + __ldg(bdg);
    }
}

// 8-lane group processes 4 edges (software-pipelined):
//   - 4 bond loads issue together (MLP 4)
//   - up to 8 independent y float4 loads issue together (MLP 8)
//   - 3-level shfl reduce per edge; lanes 0..3 then run the 4 tails in parallel
//   - per-block energy accumulation (removes the reduce_mean kernel)
__global__ void edge_kernel(const float* __restrict__ y,
                            const float* __restrict__ bondlength,
                            const int* __restrict__ src,
                            const int* __restrict__ dst,
                            const float* __restrict__ Weg,
                            const float* __restrict__ beg,
                            float* __restrict__ atom,
                            float* __restrict__ out0,
                            int E, float invN)
{
    __shared__ float sWeg[HID];
    __shared__ float sEsum;
    int tid = threadIdx.x;
    if (tid < HID) sWeg[tid] = Weg[tid];
    if (tid == 0)  sEsum = 0.0f;
    __syncthreads();

    int gt  = blockIdx.x * blockDim.x + tid;
    int grp = gt >> 3;
    int sub = gt & 7;
    int e0  = grp * 4;

    float r0 = (e0     < E) ? __ldg(bondlength + e0)     : 5.0f;
    float r1 = (e0 + 1 < E) ? __ldg(bondlength + e0 + 1) : 5.0f;
    float r2 = (e0 + 2 < E) ? __ldg(bondlength + e0 + 2) : 5.0f;
    float r3 = (e0 + 3 < E) ? __ldg(bondlength + e0 + 3) : 5.0f;

    float4 wa = *(const float4*)(sWeg + sub * 8);
    float4 wb = *(const float4*)(sWeg + sub * 8 + 4);

    float d0 = 0.f, d1 = 0.f, d2 = 0.f, d3 = 0.f;
    const float* ybase = y + (size_t)e0 * HID + sub * 8;
    if (r0 <= 4.0f) {
        float4 a = *(const float4*)(ybase);
        float4 b = *(const float4*)(ybase + 4);
        d0 = a.x*wa.x + a.y*wa.y + a.z*wa.z + a.w*wa.w
           + b.x*wb.x + b.y*wb.y + b.z*wb.z + b.w*wb.w;
    }
    if (r1 <= 4.0f) {
        float4 a = *(const float4*)(ybase + HID);
        float4 b = *(const float4*)(ybase + HID + 4);
        d1 = a.x*wa.x + a.y*wa.y + a.z*wa.z + a.w*wa.w
           + b.x*wb.x + b.y*wb.y + b.z*wb.z + b.w*wb.w;
    }
    if (r2 <= 4.0f) {
        float4 a = *(const float4*)(ybase + 2 * HID);
        float4 b = *(const float4*)(ybase + 2 * HID + 4);
        d2 = a.x*wa.x + a.y*wa.y + a.z*wa.z + a.w*wa.w
           + b.x*wb.x + b.y*wb.y + b.z*wb.z + b.w*wb.w;
    }
    if (r3 <= 4.0f) {
        float4 a = *(const float4*)(ybase + 3 * HID);
        float4 b = *(const float4*)(ybase + 3 * HID + 4);
        d3 = a.x*wa.x + a.y*wa.y + a.z*wa.z + a.w*wa.w
           + b.x*wb.x + b.y*wb.y + b.z*wb.z + b.w*wb.w;
    }

    // reduce each edge's partial within the 8-lane group
#pragma unroll
    for (int off = 4; off >= 1; off >>= 1) {
        d0 += __shfl_xor_sync(0xffffffffu, d0, off);
        d1 += __shfl_xor_sync(0xffffffffu, d1, off);
        d2 += __shfl_xor_sync(0xffffffffu, d2, off);
        d3 += __shfl_xor_sync(0xffffffffu, d3, off);
    }

    // lanes 0..3 each take one edge's tail
    float V = 0.0f;
    int   e = e0 + sub;
    if (sub < 4 && e < E) {
        float r = (sub == 0) ? r0 : (sub == 1) ? r1 : (sub == 2) ? r2 : r3;
        float d = (sub == 0) ? d0 : (sub == 1) ? d1 : (sub == 2) ? d2 : d3;
        if (r <= 4.0f) {
            int s  = src[e];
            int dn = dst[e];
            float4 ps = *(const float4*)(g_srcTab + (size_t)s * 8);
            float  gs = g_srcTab[(size_t)s * 8 + 4];
            float4 pd = *(const float4*)(g_dstTab + (size_t)dn * 8);
            float  gd = g_dstTab[(size_t)dn * 8 + 4];

            float m  = gs + gd + d + __ldg(beg);
            float bo = 1.0f / (1.0f + __expf(-m));

            float p0 = __expf(ps.x + pd.x);
            float p1 = __expf(ps.y + pd.y);
            float p2 = __expf(ps.z + pd.z);
            float p3 = __expf(ps.w + pd.w);

            float frep = p0 * __expf(-p1 * r);
            float fatt = p2 * __expf(-p3 * r);

            // cutoff: 1 for r<3.8; 0.5-0.5*sin(pi*(r-3.9)/0.2) for 3.8<=r<=4.0
            float c = 1.0f;
            if (r >= 3.8f)
                c = 0.5f - 0.5f * __sinf(CUDART_PI_F * (r - 3.9f) * 5.0f);

            V = c * (frep - bo * fatt);
            atomicAdd(atom + dn, V);
        }
    }

    // block-level energy accumulation: warp reduce -> smem -> one global atomic
#pragma unroll
    for (int off = 16; off >= 1; off >>= 1)
        V += __shfl_xor_sync(0xffffffffu, V, off);
    if ((tid & 31) == 0 && V != 0.0f)
        atomicAdd(&sEsum, V);
    __syncthreads();
    if (tid == 0)
        atomicAdd(out0, sEsum * invN);
}

extern "C" void kernel_launch(void* const* d_in, const int* in_sizes, int n_in,
                              void* d_out, int out_size)
{
    const float* x    = (const float*)d_in[0];
    const float* x0   = (const float*)d_in[1];
    const float* y    = (const float*)d_in[2];
    const float* bond = (const float*)d_in[3];
    const int*   src  = (const int*)d_in[4];
    const int*   dst  = (const int*)d_in[5];
    const float* Wsg  = (const float*)d_in[6];
    const float* bsg  = (const float*)d_in[7];
    const float* Wdg  = (const float*)d_in[8];
    const float* bdg  = (const float*)d_in[9];
    const float* Weg  = (const float*)d_in[10];
    const float* beg  = (const float*)d_in[11];
    const float* Wsp  = (const float*)d_in[12];
    const float* bsp  = (const float*)d_in[13];
    const float* Wdp  = (const float*)d_in[14];

    const int N = in_sizes[0] / HID;   // 50000
    const int E = in_sizes[3];         // 1600000

    float* out = (float*)d_out;        // out[0] = energy, out[1..N] = atomwise

    // 1) zero the full output (energy accumulator + atomwise accumulators)
    zero_kernel<<<(out_size + 255) / 256, 256>>>(out, out_size);

    // 2) per-node gate/param precompute (8 lanes/node)
    node_kernel<<<(N * 8 + 255) / 256, 256>>>(x, x0, Wsg, bsg, Wdg, bdg,
                                              Wsp, bsp, Wdp, N);

    // 3) per-edge fused: dot + gate + pair potential + scatter + energy
    //    8 lanes per group, 4 edges per group -> 2 threads per edge
    long long ethreads = ((long long)E + 3) / 4 * 8;
    edge_kernel<<<(int)((ethreads + 255) / 256), 256>>>(y, bond, src, dst,
                                                        Weg, beg, out + 1, out,
                                                        E, 1.0f / (float)N);
}

// round 5
// speedup vs baseline: 2.3292x; 1.0682x over previous
#include <cuda_runtime.h>
#include <math_constants.h>

#define HID   64
#define MAXN  50000

// Per-node precomputed tables, stride 8 floats for float4 alignment.
// srcTab[n*8 + 0..3] = ps (x0·Wsp + bsp), [n*8+4] = gs (x·Wsg + bsg)
// dstTab[n*8 + 0..3] = pd (x0·Wdp),       [n*8+4] = gd (x·Wdg + bdg)
__device__ float g_srcTab[MAXN * 8];
__device__ float g_dstTab[MAXN * 8];

// 8 lanes per node; lane handles elements [sub*4 .. sub*4+3] and [32+sub*4 ..].
// Also zeroes the output accumulators (atom[node], and out0 by node 0).
__global__ void node_kernel(const float* __restrict__ x,
                            const float* __restrict__ x0,
                            const float* __restrict__ Wsg, const float* __restrict__ bsg,
                            const float* __restrict__ Wdg, const float* __restrict__ bdg,
                            const float* __restrict__ Wsp, const float* __restrict__ bsp,
                            const float* __restrict__ Wdp,
                            float* __restrict__ atom, float* __restrict__ out0,
                            int n)
{
    int t    = blockIdx.x * blockDim.x + threadIdx.x;
    int node = t >> 3;
    int sub  = t & 7;
    if (node >= n) return;

    const size_t base = (size_t)node * HID;
    const int h0 = sub * 4;        // first element of chunk A
    const int h1 = 32 + sub * 4;   // first element of chunk B

    float4 xa  = *(const float4*)(x  + base + h0);
    float4 xb  = *(const float4*)(x  + base + h1);
    float4 x0a = *(const float4*)(x0 + base + h0);
    float4 x0b = *(const float4*)(x0 + base + h1);

    float gs = 0.f, gd = 0.f;
    float ps0 = 0.f, ps1 = 0.f, ps2 = 0.f, ps3 = 0.f;
    float pd0 = 0.f, pd1 = 0.f, pd2 = 0.f, pd3 = 0.f;

    const float* xav  = (const float*)&xa;
    const float* xbv  = (const float*)&xb;
    const float* x0av = (const float*)&x0a;
    const float* x0bv = (const float*)&x0b;

#pragma unroll
    for (int k = 0; k < 4; k++) {
        int ha = h0 + k, hb = h1 + k;
        gs += xav[k] * __ldg(Wsg + ha) + xbv[k] * __ldg(Wsg + hb);
        gd += xav[k] * __ldg(Wdg + ha) + xbv[k] * __ldg(Wdg + hb);
        float4 wsa = *(const float4*)(Wsp + ha * 4);
        float4 wsb = *(const float4*)(Wsp + hb * 4);
        float4 wda = *(const float4*)(Wdp + ha * 4);
        float4 wdb = *(const float4*)(Wdp + hb * 4);
        ps0 += x0av[k] * wsa.x + x0bv[k] * wsb.x;
        ps1 += x0av[k] * wsa.y + x0bv[k] * wsb.y;
        ps2 += x0av[k] * wsa.z + x0bv[k] * wsb.z;
        ps3 += x0av[k] * wsa.w + x0bv[k] * wsb.w;
        pd0 += x0av[k] * wda.x + x0bv[k] * wdb.x;
        pd1 += x0av[k] * wda.y + x0bv[k] * wdb.y;
        pd2 += x0av[k] * wda.z + x0bv[k] * wdb.z;
        pd3 += x0av[k] * wda.w + x0bv[k] * wdb.w;
    }

    // reduce across the 8 lanes of this node
#pragma unroll
    for (int off = 4; off >= 1; off >>= 1) {
        gs  += __shfl_xor_sync(0xffffffffu, gs,  off);
        gd  += __shfl_xor_sync(0xffffffffu, gd,  off);
        ps0 += __shfl_xor_sync(0xffffffffu, ps0, off);
        ps1 += __shfl_xor_sync(0xffffffffu, ps1, off);
        ps2 += __shfl_xor_sync(0xffffffffu, ps2, off);
        ps3 += __shfl_xor_sync(0xffffffffu, ps3, off);
        pd0 += __shfl_xor_sync(0xffffffffu, pd0, off);
        pd1 += __shfl_xor_sync(0xffffffffu, pd1, off);
        pd2 += __shfl_xor_sync(0xffffffffu, pd2, off);
        pd3 += __shfl_xor_sync(0xffffffffu, pd3, off);
    }

    if (sub == 0) {
        float4 psv = make_float4(ps0 + __ldg(bsp + 0), ps1 + __ldg(bsp + 1),
                                 ps2 + __ldg(bsp + 2), ps3 + __ldg(bsp + 3));
        float4 pdv = make_float4(pd0, pd1, pd2, pd3);
        *(float4*)(g_srcTab + (size_t)node * 8) = psv;
        g_srcTab[(size_t)node * 8 + 4] = gs + __ldg(bsg);
        *(float4*)(g_dstTab + (size_t)node * 8) = pdv;
        g_dstTab[(size_t)node * 8 + 4] = gd + __ldg(bdg);
        atom[node] = 0.0f;                 // zero the scatter accumulator
        if (node == 0) *out0 = 0.0f;       // zero the energy accumulator
    }
}

// 8-lane group processes 8 edges:
//   - 8 bond loads issue together (MLP 8)
//   - y rows loaded pairwise (4 independent float4 loads in flight)
//   - per-edge 3-level shfl reduce; then ALL 32 lanes of the warp run one
//     edge tail each (gathers + exp + scatter-add)
//   - per-block energy accumulation (no separate reduce kernel)
__global__ void __launch_bounds__(256)
edge_kernel(const float* __restrict__ y,
            const float* __restrict__ bondlength,
            const int* __restrict__ src,
            const int* __restrict__ dst,
            const float* __restrict__ Weg,
            const float* __restrict__ beg,
            float* __restrict__ atom,
            float* __restrict__ out0,
            int E, float invN)
{
    __shared__ float sWeg[HID];
    __shared__ float sEsum;
    int tid = threadIdx.x;
    if (tid < HID) sWeg[tid] = Weg[tid];
    if (tid == 0)  sEsum = 0.0f;
    __syncthreads();

    int gt  = blockIdx.x * blockDim.x + tid;
    int grp = gt >> 3;
    int sub = gt & 7;
    int e0  = grp * 8;

    float r[8];
#pragma unroll
    for (int p = 0; p < 8; p++)
        r[p] = (e0 + p < E) ? __ldg(bondlength + e0 + p) : 5.0f;

    float4 wa = *(const float4*)(sWeg + sub * 8);
    float4 wb = *(const float4*)(sWeg + sub * 8 + 4);

    float d[8];
    const float* ybase = y + (size_t)e0 * HID + sub * 8;
#pragma unroll
    for (int p = 0; p < 8; p += 2) {
        float da = 0.f, db = 0.f;
        if (r[p] <= 4.0f) {
            float4 a = *(const float4*)(ybase + (size_t)p * HID);
            float4 b = *(const float4*)(ybase + (size_t)p * HID + 4);
            da = a.x*wa.x + a.y*wa.y + a.z*wa.z + a.w*wa.w
               + b.x*wb.x + b.y*wb.y + b.z*wb.z + b.w*wb.w;
        }
        if (r[p + 1] <= 4.0f) {
            float4 a = *(const float4*)(ybase + (size_t)(p + 1) * HID);
            float4 b = *(const float4*)(ybase + (size_t)(p + 1) * HID + 4);
            db = a.x*wa.x + a.y*wa.y + a.z*wa.z + a.w*wa.w
               + b.x*wb.x + b.y*wb.y + b.z*wb.z + b.w*wb.w;
        }
        d[p] = da; d[p + 1] = db;
    }

    // reduce each edge's partial within the 8-lane group
#pragma unroll
    for (int off = 4; off >= 1; off >>= 1) {
#pragma unroll
        for (int p = 0; p < 8; p++)
            d[p] += __shfl_xor_sync(0xffffffffu, d[p], off);
    }

    // every lane takes one edge's tail: lane handles edge e0 + sub
    float V = 0.0f;
    int   e = e0 + sub;
    {
        // constant-unrolled selects (no dynamic register indexing)
        float myr = r[0], myd = d[0];
#pragma unroll
        for (int p = 1; p < 8; p++) {
            if (sub == p) { myr = r[p]; myd = d[p]; }
        }
        if (e < E && myr <= 4.0f) {
            int s  = src[e];
            int dn = dst[e];
            float4 ps = *(const float4*)(g_srcTab + (size_t)s * 8);
            float  gs = g_srcTab[(size_t)s * 8 + 4];
            float4 pd = *(const float4*)(g_dstTab + (size_t)dn * 8);
            float  gd = g_dstTab[(size_t)dn * 8 + 4];

            float m  = gs + gd + myd + __ldg(beg);
            float bo = 1.0f / (1.0f + __expf(-m));

            float p0 = __expf(ps.x + pd.x);
            float p1 = __expf(ps.y + pd.y);
            float p2 = __expf(ps.z + pd.z);
            float p3 = __expf(ps.w + pd.w);

            float frep = p0 * __expf(-p1 * myr);
            float fatt = p2 * __expf(-p3 * myr);

            // cutoff: 1 for r<3.8; 0.5-0.5*sin(pi*(r-3.9)/0.2) for 3.8<=r<=4.0
            float c = 1.0f;
            if (myr >= 3.8f)
                c = 0.5f - 0.5f * __sinf(CUDART_PI_F * (myr - 3.9f) * 5.0f);

            V = c * (frep - bo * fatt);
            atomicAdd(atom + dn, V);
        }
    }

    // block-level energy accumulation: warp reduce -> smem -> one global atomic
#pragma unroll
    for (int off = 16; off >= 1; off >>= 1)
        V += __shfl_xor_sync(0xffffffffu, V, off);
    if ((tid & 31) == 0 && V != 0.0f)
        atomicAdd(&sEsum, V);
    __syncthreads();
    if (tid == 0)
        atomicAdd(out0, sEsum * invN);
}

extern "C" void kernel_launch(void* const* d_in, const int* in_sizes, int n_in,
                              void* d_out, int out_size)
{
    const float* x    = (const float*)d_in[0];
    const float* x0   = (const float*)d_in[1];
    const float* y    = (const float*)d_in[2];
    const float* bond = (const float*)d_in[3];
    const int*   src  = (const int*)d_in[4];
    const int*   dst  = (const int*)d_in[5];
    const float* Wsg  = (const float*)d_in[6];
    const float* bsg  = (const float*)d_in[7];
    const float* Wdg  = (const float*)d_in[8];
    const float* bdg  = (const float*)d_in[9];
    const float* Weg  = (const float*)d_in[10];
    const float* beg  = (const float*)d_in[11];
    const float* Wsp  = (const float*)d_in[12];
    const float* bsp  = (const float*)d_in[13];
    const float* Wdp  = (const float*)d_in[14];

    const int N = in_sizes[0] / HID;   // 50000
    const int E = in_sizes[3];         // 1600000

    float* out = (float*)d_out;        // out[0] = energy, out[1..N] = atomwise

    // 1) per-node gate/param precompute + zero the output accumulators
    node_kernel<<<(N * 8 + 255) / 256, 256>>>(x, x0, Wsg, bsg, Wdg, bdg,
                                              Wsp, bsp, Wdp, out + 1, out, N);

    // 2) per-edge fused: dot + gate + pair potential + scatter + energy
    //    8 lanes per group, 8 edges per group -> 1 thread per edge
    long long ethreads = ((long long)E + 7) / 8 * 8;
    edge_kernel<<<(int)((ethreads + 255) / 256), 256>>>(y, bond, src, dst,
                                                        Weg, beg, out + 1, out,
                                                        E, 1.0f / (float)N);
}

// round 6
// speedup vs baseline: 2.3754x; 1.0198x over previous
#include <cuda_runtime.h>
#include <math_constants.h>

#define HID   64
#define MAXN  50000

// Per-node precomputed tables, stride 8 floats for float4 alignment.
// srcTab[n*8 + 0..3] = ps (x0·Wsp + bsp), [n*8+4] = gs (x·Wsg + bsg)
// dstTab[n*8 + 0..3] = pd (x0·Wdp),       [n*8+4] = gd (x·Wdg + bdg)
__device__ float g_srcTab[MAXN * 8];
__device__ float g_dstTab[MAXN * 8];

// 8 lanes per node; lane handles elements [sub*4 .. sub*4+3] and [32+sub*4 ..].
// Uses a butterfly transpose-reduce so lane `sub` ends with param[sub]; stores
// are distributed across lanes. Also zeroes the output accumulators.
__global__ void node_kernel(const float* __restrict__ x,
                            const float* __restrict__ x0,
                            const float* __restrict__ Wsg, const float* __restrict__ bsg,
                            const float* __restrict__ Wdg, const float* __restrict__ bdg,
                            const float* __restrict__ Wsp, const float* __restrict__ bsp,
                            const float* __restrict__ Wdp,
                            float* __restrict__ atom, float* __restrict__ out0,
                            int n)
{
    int t    = blockIdx.x * blockDim.x + threadIdx.x;
    int node = t >> 3;
    int sub  = t & 7;
    if (node >= n) return;

    const size_t base = (size_t)node * HID;
    const int h0 = sub * 4;        // first element of chunk A
    const int h1 = 32 + sub * 4;   // first element of chunk B

    float4 xa  = *(const float4*)(x  + base + h0);
    float4 xb  = *(const float4*)(x  + base + h1);
    float4 x0a = *(const float4*)(x0 + base + h0);
    float4 x0b = *(const float4*)(x0 + base + h1);

    float gs = 0.f, gd = 0.f;
    float v[8];                    // 0..3 = ps partials, 4..7 = pd partials
#pragma unroll
    for (int p = 0; p < 8; p++) v[p] = 0.f;

    const float* xav  = (const float*)&xa;
    const float* xbv  = (const float*)&xb;
    const float* x0av = (const float*)&x0a;
    const float* x0bv = (const float*)&x0b;

#pragma unroll
    for (int k = 0; k < 4; k++) {
        int ha = h0 + k, hb = h1 + k;
        gs += xav[k] * __ldg(Wsg + ha) + xbv[k] * __ldg(Wsg + hb);
        gd += xav[k] * __ldg(Wdg + ha) + xbv[k] * __ldg(Wdg + hb);
        float4 wsa = *(const float4*)(Wsp + ha * 4);
        float4 wsb = *(const float4*)(Wsp + hb * 4);
        float4 wda = *(const float4*)(Wdp + ha * 4);
        float4 wdb = *(const float4*)(Wdp + hb * 4);
        v[0] += x0av[k] * wsa.x + x0bv[k] * wsb.x;
        v[1] += x0av[k] * wsa.y + x0bv[k] * wsb.y;
        v[2] += x0av[k] * wsa.z + x0bv[k] * wsb.z;
        v[3] += x0av[k] * wsa.w + x0bv[k] * wsb.w;
        v[4] += x0av[k] * wda.x + x0bv[k] * wdb.x;
        v[5] += x0av[k] * wda.y + x0bv[k] * wdb.y;
        v[6] += x0av[k] * wda.z + x0bv[k] * wdb.z;
        v[7] += x0av[k] * wda.w + x0bv[k] * wdb.w;
    }

    // transpose-reduce: 7 shuffles; lane sub ends with sum over group of v[sub]
    bool hi4 = (sub & 4) != 0;
    float a0k = hi4 ? v[4] : v[0], a0s = hi4 ? v[0] : v[4];
    float a1k = hi4 ? v[5] : v[1], a1s = hi4 ? v[1] : v[5];
    float a2k = hi4 ? v[6] : v[2], a2s = hi4 ? v[2] : v[6];
    float a3k = hi4 ? v[7] : v[3], a3s = hi4 ? v[3] : v[7];
    a0k += __shfl_xor_sync(0xffffffffu, a0s, 4);
    a1k += __shfl_xor_sync(0xffffffffu, a1s, 4);
    a2k += __shfl_xor_sync(0xffffffffu, a2s, 4);
    a3k += __shfl_xor_sync(0xffffffffu, a3s, 4);
    bool hi2 = (sub & 2) != 0;
    float b0k = hi2 ? a2k : a0k, b0s = hi2 ? a0k : a2k;
    float b1k = hi2 ? a3k : a1k, b1s = hi2 ? a1k : a3k;
    b0k += __shfl_xor_sync(0xffffffffu, b0s, 2);
    b1k += __shfl_xor_sync(0xffffffffu, b1s, 2);
    bool hi1 = (sub & 1) != 0;
    float ck = hi1 ? b1k : b0k, cs = hi1 ? b0k : b1k;
    ck += __shfl_xor_sync(0xffffffffu, cs, 1);

    // plain reduce for the two gate scalars (6 shuffles)
#pragma unroll
    for (int off = 4; off >= 1; off >>= 1) {
        gs += __shfl_xor_sync(0xffffffffu, gs, off);
        gd += __shfl_xor_sync(0xffffffffu, gd, off);
    }

    // distributed stores: lane sub<4 -> srcTab param, sub>=4 -> dstTab param
    if (sub < 4)
        g_srcTab[(size_t)node * 8 + sub] = ck + __ldg(bsp + sub);
    else
        g_dstTab[(size_t)node * 8 + (sub - 4)] = ck;
    if (sub == 0) {
        g_srcTab[(size_t)node * 8 + 4] = gs + __ldg(bsg);
        g_dstTab[(size_t)node * 8 + 4] = gd + __ldg(bdg);
        atom[node] = 0.0f;                 // zero the scatter accumulator
        if (node == 0) *out0 = 0.0f;       // zero the energy accumulator
    }
}

// 8-lane group processes 8 edges:
//   - 8 bond loads issue together (MLP 8)
//   - y rows loaded pairwise (4 independent float4 loads in flight)
//   - 7-shuffle transpose-reduce leaves lane sub holding edge e0+sub's dot
//   - ALL 32 lanes then run one edge tail each (gathers + exp + scatter-add)
//   - per-block energy accumulation (no separate reduce kernel)
__global__ void __launch_bounds__(256, 6)
edge_kernel(const float* __restrict__ y,
            const float* __restrict__ bondlength,
            const int* __restrict__ src,
            const int* __restrict__ dst,
            const float* __restrict__ Weg,
            const float* __restrict__ beg,
            float* __restrict__ atom,
            float* __restrict__ out0,
            int E, float invN)
{
    __shared__ float sWeg[HID];
    __shared__ float sEsum;
    int tid = threadIdx.x;
    if (tid < HID) sWeg[tid] = Weg[tid];
    if (tid == 0)  sEsum = 0.0f;
    __syncthreads();

    int gt  = blockIdx.x * blockDim.x + tid;
    int grp = gt >> 3;
    int sub = gt & 7;
    int e0  = grp * 8;

    float r[8];
#pragma unroll
    for (int p = 0; p < 8; p++)
        r[p] = (e0 + p < E) ? __ldg(bondlength + e0 + p) : 5.0f;

    float4 wa = *(const float4*)(sWeg + sub * 8);
    float4 wb = *(const float4*)(sWeg + sub * 8 + 4);

    float d[8];
    const float* ybase = y + (size_t)e0 * HID + sub * 8;
#pragma unroll
    for (int p = 0; p < 8; p += 2) {
        float da = 0.f, db = 0.f;
        if (r[p] <= 4.0f) {
            float4 a = *(const float4*)(ybase + (size_t)p * HID);
            float4 b = *(const float4*)(ybase + (size_t)p * HID + 4);
            da = a.x*wa.x + a.y*wa.y + a.z*wa.z + a.w*wa.w
               + b.x*wb.x + b.y*wb.y + b.z*wb.z + b.w*wb.w;
        }
        if (r[p + 1] <= 4.0f) {
            float4 a = *(const float4*)(ybase + (size_t)(p + 1) * HID);
            float4 b = *(const float4*)(ybase + (size_t)(p + 1) * HID + 4);
            db = a.x*wa.x + a.y*wa.y + a.z*wa.z + a.w*wa.w
               + b.x*wb.x + b.y*wb.y + b.z*wb.z + b.w*wb.w;
        }
        d[p] = da; d[p + 1] = db;
    }

    // transpose-reduce: 7 shuffles; lane sub ends with the full dot of edge e0+sub
    bool hi4 = (sub & 4) != 0;
    float a0k = hi4 ? d[4] : d[0], a0s = hi4 ? d[0] : d[4];
    float a1k = hi4 ? d[5] : d[1], a1s = hi4 ? d[1] : d[5];
    float a2k = hi4 ? d[6] : d[2], a2s = hi4 ? d[2] : d[6];
    float a3k = hi4 ? d[7] : d[3], a3s = hi4 ? d[3] : d[7];
    a0k += __shfl_xor_sync(0xffffffffu, a0s, 4);
    a1k += __shfl_xor_sync(0xffffffffu, a1s, 4);
    a2k += __shfl_xor_sync(0xffffffffu, a2s, 4);
    a3k += __shfl_xor_sync(0xffffffffu, a3s, 4);
    bool hi2 = (sub & 2) != 0;
    float b0k = hi2 ? a2k : a0k, b0s = hi2 ? a0k : a2k;
    float b1k = hi2 ? a3k : a1k, b1s = hi2 ? a1k : a3k;
    b0k += __shfl_xor_sync(0xffffffffu, b0s, 2);
    b1k += __shfl_xor_sync(0xffffffffu, b1s, 2);
    bool hi1 = (sub & 1) != 0;
    float myd = hi1 ? b1k : b0k, cs = hi1 ? b0k : b1k;
    myd += __shfl_xor_sync(0xffffffffu, cs, 1);

    // every lane takes one edge's tail: lane handles edge e0 + sub
    float V = 0.0f;
    int   e = e0 + sub;
    if (e < E) {
        float myr = __ldg(bondlength + e);   // L1 hit; avoids keeping r[] alive
        if (myr <= 4.0f) {
            int s  = src[e];
            int dn = dst[e];
            float4 ps = *(const float4*)(g_srcTab + (size_t)s * 8);
            float  gs = g_srcTab[(size_t)s * 8 + 4];
            float4 pd = *(const float4*)(g_dstTab + (size_t)dn * 8);
            float  gd = g_dstTab[(size_t)dn * 8 + 4];

            float m  = gs + gd + myd + __ldg(beg);
            float bo = 1.0f / (1.0f + __expf(-m));

            float p0 = __expf(ps.x + pd.x);
            float p1 = __expf(ps.y + pd.y);
            float p2 = __expf(ps.z + pd.z);
            float p3 = __expf(ps.w + pd.w);

            float frep = p0 * __expf(-p1 * myr);
            float fatt = p2 * __expf(-p3 * myr);

            // cutoff: 1 for r<3.8; 0.5-0.5*sin(pi*(r-3.9)/0.2) for 3.8<=r<=4.0
            float c = 1.0f;
            if (myr >= 3.8f)
                c = 0.5f - 0.5f * __sinf(CUDART_PI_F * (myr - 3.9f) * 5.0f);

            V = c * (frep - bo * fatt);
            atomicAdd(atom + dn, V);
        }
    }

    // block-level energy accumulation: warp reduce -> smem -> one global atomic
#pragma unroll
    for (int off = 16; off >= 1; off >>= 1)
        V += __shfl_xor_sync(0xffffffffu, V, off);
    if ((tid & 31) == 0 && V != 0.0f)
        atomicAdd(&sEsum, V);
    __syncthreads();
    if (tid == 0)
        atomicAdd(out0, sEsum * invN);
}

extern "C" void kernel_launch(void* const* d_in, const int* in_sizes, int n_in,
                              void* d_out, int out_size)
{
    const float* x    = (const float*)d_in[0];
    const float* x0   = (const float*)d_in[1];
    const float* y    = (const float*)d_in[2];
    const float* bond = (const float*)d_in[3];
    const int*   src  = (const int*)d_in[4];
    const int*   dst  = (const int*)d_in[5];
    const float* Wsg  = (const float*)d_in[6];
    const float* bsg  = (const float*)d_in[7];
    const float* Wdg  = (const float*)d_in[8];
    const float* bdg  = (const float*)d_in[9];
    const float* Weg  = (const float*)d_in[10];
    const float* beg  = (const float*)d_in[11];
    const float* Wsp  = (const float*)d_in[12];
    const float* bsp  = (const float*)d_in[13];
    const float* Wdp  = (const float*)d_in[14];

    const int N = in_sizes[0] / HID;   // 50000
    const int E = in_sizes[3];         // 1600000

    float* out = (float*)d_out;        // out[0] = energy, out[1..N] = atomwise

    // 1) per-node gate/param precompute + zero the output accumulators
    node_kernel<<<(N * 8 + 255) / 256, 256>>>(x, x0, Wsg, bsg, Wdg, bdg,
                                              Wsp, bsp, Wdp, out + 1, out, N);

    // 2) per-edge fused: dot + gate + pair potential + scatter + energy
    //    8 lanes per group, 8 edges per group -> 1 thread per edge
    long long ethreads = ((long long)E + 7) / 8 * 8;
    edge_kernel<<<(int)((ethreads + 255) / 256), 256>>>(y, bond, src, dst,
                                                        Weg, beg, out + 1, out,
                                                        E, 1.0f / (float)N);
}

// round 7
// speedup vs baseline: 2.5598x; 1.0776x over previous
#include <cuda_runtime.h>
#include <math_constants.h>

#define HID   64
#define MAXN  50000

// Per-node precomputed tables, stride 8 floats for float4 alignment.
// srcTab[n*8 + 0..3] = ps (x0·Wsp + bsp), [n*8+4] = gs (x·Wsg + bsg)
// dstTab[n*8 + 0..3] = pd (x0·Wdp),       [n*8+4] = gd (x·Wdg + bdg)
__device__ float g_srcTab[MAXN * 8];
__device__ float g_dstTab[MAXN * 8];

// 8 lanes per node; lane handles elements [sub*4 .. sub*4+3] and [32+sub*4 ..].
// Uses a butterfly transpose-reduce so lane `sub` ends with param[sub]; stores
// are distributed across lanes. Also zeroes the output accumulators.
__global__ void node_kernel(const float* __restrict__ x,
                            const float* __restrict__ x0,
                            const float* __restrict__ Wsg, const float* __restrict__ bsg,
                            const float* __restrict__ Wdg, const float* __restrict__ bdg,
                            const float* __restrict__ Wsp, const float* __restrict__ bsp,
                            const float* __restrict__ Wdp,
                            float* __restrict__ atom, float* __restrict__ out0,
                            int n)
{
    int t    = blockIdx.x * blockDim.x + threadIdx.x;
    int node = t >> 3;
    int sub  = t & 7;
    if (node >= n) return;

    const size_t base = (size_t)node * HID;
    const int h0 = sub * 4;        // first element of chunk A
    const int h1 = 32 + sub * 4;   // first element of chunk B

    float4 xa  = *(const float4*)(x  + base + h0);
    float4 xb  = *(const float4*)(x  + base + h1);
    float4 x0a = *(const float4*)(x0 + base + h0);
    float4 x0b = *(const float4*)(x0 + base + h1);

    float gs = 0.f, gd = 0.f;
    float v[8];                    // 0..3 = ps partials, 4..7 = pd partials
#pragma unroll
    for (int p = 0; p < 8; p++) v[p] = 0.f;

    const float* xav  = (const float*)&xa;
    const float* xbv  = (const float*)&xb;
    const float* x0av = (const float*)&x0a;
    const float* x0bv = (const float*)&x0b;

#pragma unroll
    for (int k = 0; k < 4; k++) {
        int ha = h0 + k, hb = h1 + k;
        gs += xav[k] * __ldg(Wsg + ha) + xbv[k] * __ldg(Wsg + hb);
        gd += xav[k] * __ldg(Wdg + ha) + xbv[k] * __ldg(Wdg + hb);
        float4 wsa = *(const float4*)(Wsp + ha * 4);
        float4 wsb = *(const float4*)(Wsp + hb * 4);
        float4 wda = *(const float4*)(Wdp + ha * 4);
        float4 wdb = *(const float4*)(Wdp + hb * 4);
        v[0] += x0av[k] * wsa.x + x0bv[k] * wsb.x;
        v[1] += x0av[k] * wsa.y + x0bv[k] * wsb.y;
        v[2] += x0av[k] * wsa.z + x0bv[k] * wsb.z;
        v[3] += x0av[k] * wsa.w + x0bv[k] * wsb.w;
        v[4] += x0av[k] * wda.x + x0bv[k] * wdb.x;
        v[5] += x0av[k] * wda.y + x0bv[k] * wdb.y;
        v[6] += x0av[k] * wda.z + x0bv[k] * wdb.z;
        v[7] += x0av[k] * wda.w + x0bv[k] * wdb.w;
    }

    // transpose-reduce: 7 shuffles; lane sub ends with sum over group of v[sub]
    bool hi4 = (sub & 4) != 0;
    float a0k = hi4 ? v[4] : v[0], a0s = hi4 ? v[0] : v[4];
    float a1k = hi4 ? v[5] : v[1], a1s = hi4 ? v[1] : v[5];
    float a2k = hi4 ? v[6] : v[2], a2s = hi4 ? v[2] : v[6];
    float a3k = hi4 ? v[7] : v[3], a3s = hi4 ? v[3] : v[7];
    a0k += __shfl_xor_sync(0xffffffffu, a0s, 4);
    a1k += __shfl_xor_sync(0xffffffffu, a1s, 4);
    a2k += __shfl_xor_sync(0xffffffffu, a2s, 4);
    a3k += __shfl_xor_sync(0xffffffffu, a3s, 4);
    bool hi2 = (sub & 2) != 0;
    float b0k = hi2 ? a2k : a0k, b0s = hi2 ? a0k : a2k;
    float b1k = hi2 ? a3k : a1k, b1s = hi2 ? a1k : a3k;
    b0k += __shfl_xor_sync(0xffffffffu, b0s, 2);
    b1k += __shfl_xor_sync(0xffffffffu, b1s, 2);
    bool hi1 = (sub & 1) != 0;
    float ck = hi1 ? b1k : b0k, cs = hi1 ? b0k : b1k;
    ck += __shfl_xor_sync(0xffffffffu, cs, 1);

    // plain reduce for the two gate scalars (6 shuffles)
#pragma unroll
    for (int off = 4; off >= 1; off >>= 1) {
        gs += __shfl_xor_sync(0xffffffffu, gs, off);
        gd += __shfl_xor_sync(0xffffffffu, gd, off);
    }

    // distributed stores: lane sub<4 -> srcTab param, sub>=4 -> dstTab param
    if (sub < 4)
        g_srcTab[(size_t)node * 8 + sub] = ck + __ldg(bsp + sub);
    else
        g_dstTab[(size_t)node * 8 + (sub - 4)] = ck;
    if (sub == 0) {
        g_srcTab[(size_t)node * 8 + 4] = gs + __ldg(bsg);
        g_dstTab[(size_t)node * 8 + 4] = gd + __ldg(bdg);
        atom[node] = 0.0f;                 // zero the scatter accumulator
        if (node == 0) *out0 = 0.0f;       // zero the energy accumulator
    }
}

// 8-lane group processes 8 edges:
//   - 8 bond loads issue together (MLP 8)
//   - y loaded as two CONTIGUOUS 128B lines per row (lane sub covers floats
//     [sub*4, sub*4+4) and [32+sub*4, ...)): 1 L1tex wavefront per group per
//     instruction, the wavefront floor. __ldcs keeps the one-touch y stream
//     out of L1 so the node-table gathers can live there.
//   - 7-shuffle transpose-reduce leaves lane sub holding edge e0+sub's dot
//   - ALL 32 lanes then run one edge tail each (gathers + exp + scatter-add)
//   - per-block energy accumulation (no separate reduce kernel)
__global__ void __launch_bounds__(256, 6)
edge_kernel(const float* __restrict__ y,
            const float* __restrict__ bondlength,
            const int* __restrict__ src,
            const int* __restrict__ dst,
            const float* __restrict__ Weg,
            const float* __restrict__ beg,
            float* __restrict__ atom,
            float* __restrict__ out0,
            int E, float invN)
{
    __shared__ float sWeg[HID];
    __shared__ float sEsum;
    int tid = threadIdx.x;
    if (tid < HID) sWeg[tid] = Weg[tid];
    if (tid == 0)  sEsum = 0.0f;
    __syncthreads();

    int gt  = blockIdx.x * blockDim.x + tid;
    int grp = gt >> 3;
    int sub = gt & 7;
    int e0  = grp * 8;

    float r[8];
#pragma unroll
    for (int p = 0; p < 8; p++)
        r[p] = (e0 + p < E) ? __ldcs(bondlength + e0 + p) : 5.0f;

    float4 wa = *(const float4*)(sWeg + sub * 4);        // floats [4sub, 4sub+4)
    float4 wb = *(const float4*)(sWeg + 32 + sub * 4);   // floats [32+4sub, ...)

    float d[8];
    const float* ybase = y + (size_t)e0 * HID;
#pragma unroll
    for (int p = 0; p < 8; p += 2) {
        float da = 0.f, db = 0.f;
        if (r[p] <= 4.0f) {
            const float* row = ybase + (size_t)p * HID;
            float4 a = __ldcs((const float4*)(row + sub * 4));
            float4 b = __ldcs((const float4*)(row + 32 + sub * 4));
            da = a.x*wa.x + a.y*wa.y + a.z*wa.z + a.w*wa.w
               + b.x*wb.x + b.y*wb.y + b.z*wb.z + b.w*wb.w;
        }
        if (r[p + 1] <= 4.0f) {
            const float* row = ybase + (size_t)(p + 1) * HID;
            float4 a = __ldcs((const float4*)(row + sub * 4));
            float4 b = __ldcs((const float4*)(row + 32 + sub * 4));
            db = a.x*wa.x + a.y*wa.y + a.z*wa.z + a.w*wa.w
               + b.x*wb.x + b.y*wb.y + b.z*wb.z + b.w*wb.w;
        }
        d[p] = da; d[p + 1] = db;
    }

    // transpose-reduce: 7 shuffles; lane sub ends with the full dot of edge e0+sub
    bool hi4 = (sub & 4) != 0;
    float a0k = hi4 ? d[4] : d[0], a0s = hi4 ? d[0] : d[4];
    float a1k = hi4 ? d[5] : d[1], a1s = hi4 ? d[1] : d[5];
    float a2k = hi4 ? d[6] : d[2], a2s = hi4 ? d[2] : d[6];
    float a3k = hi4 ? d[7] : d[3], a3s = hi4 ? d[3] : d[7];
    a0k += __shfl_xor_sync(0xffffffffu, a0s, 4);
    a1k += __shfl_xor_sync(0xffffffffu, a1s, 4);
    a2k += __shfl_xor_sync(0xffffffffu, a2s, 4);
    a3k += __shfl_xor_sync(0xffffffffu, a3s, 4);
    bool hi2 = (sub & 2) != 0;
    float b0k = hi2 ? a2k : a0k, b0s = hi2 ? a0k : a2k;
    float b1k = hi2 ? a3k : a1k, b1s = hi2 ? a1k : a3k;
    b0k += __shfl_xor_sync(0xffffffffu, b0s, 2);
    b1k += __shfl_xor_sync(0xffffffffu, b1s, 2);
    bool hi1 = (sub & 1) != 0;
    float myd = hi1 ? b1k : b0k, cs = hi1 ? b0k : b1k;
    myd += __shfl_xor_sync(0xffffffffu, cs, 1);

    // every lane takes one edge's tail: lane handles edge e0 + sub
    float V = 0.0f;
    int   e = e0 + sub;
    if (e < E) {
        float myr = __ldg(bondlength + e);   // cached read; avoids keeping r[] alive
        if (myr <= 4.0f) {
            int s  = src[e];
            int dn = dst[e];
            float4 ps = *(const float4*)(g_srcTab + (size_t)s * 8);
            float  gs = g_srcTab[(size_t)s * 8 + 4];
            float4 pd = *(const float4*)(g_dstTab + (size_t)dn * 8);
            float  gd = g_dstTab[(size_t)dn * 8 + 4];

            float m  = gs + gd + myd + __ldg(beg);
            float bo = 1.0f / (1.0f + __expf(-m));

            float p0 = __expf(ps.x + pd.x);
            float p1 = __expf(ps.y + pd.y);
            float p2 = __expf(ps.z + pd.z);
            float p3 = __expf(ps.w + pd.w);

            float frep = p0 * __expf(-p1 * myr);
            float fatt = p2 * __expf(-p3 * myr);

            // cutoff: 1 for r<3.8; 0.5-0.5*sin(pi*(r-3.9)/0.2) for 3.8<=r<=4.0
            float c = 1.0f;
            if (myr >= 3.8f)
                c = 0.5f - 0.5f * __sinf(CUDART_PI_F * (myr - 3.9f) * 5.0f);

            V = c * (frep - bo * fatt);
            atomicAdd(atom + dn, V);
        }
    }

    // block-level energy accumulation: warp reduce -> smem -> one global atomic
#pragma unroll
    for (int off = 16; off >= 1; off >>= 1)
        V += __shfl_xor_sync(0xffffffffu, V, off);
    if ((tid & 31) == 0 && V != 0.0f)
        atomicAdd(&sEsum, V);
    __syncthreads();
    if (tid == 0)
        atomicAdd(out0, sEsum * invN);
}

extern "C" void kernel_launch(void* const* d_in, const int* in_sizes, int n_in,
                              void* d_out, int out_size)
{
    const float* x    = (const float*)d_in[0];
    const float* x0   = (const float*)d_in[1];
    const float* y    = (const float*)d_in[2];
    const float* bond = (const float*)d_in[3];
    const int*   src  = (const int*)d_in[4];
    const int*   dst  = (const int*)d_in[5];
    const float* Wsg  = (const float*)d_in[6];
    const float* bsg  = (const float*)d_in[7];
    const float* Wdg  = (const float*)d_in[8];
    const float* bdg  = (const float*)d_in[9];
    const float* Weg  = (const float*)d_in[10];
    const float* beg  = (const float*)d_in[11];
    const float* Wsp  = (const float*)d_in[12];
    const float* bsp  = (const float*)d_in[13];
    const float* Wdp  = (const float*)d_in[14];

    const int N = in_sizes[0] / HID;   // 50000
    const int E = in_sizes[3];         // 1600000

    float* out = (float*)d_out;        // out[0] = energy, out[1..N] = atomwise

    // 1) per-node gate/param precompute + zero the output accumulators
    node_kernel<<<(N * 8 + 255) / 256, 256>>>(x, x0, Wsg, bsg, Wdg, bdg,
                                              Wsp, bsp, Wdp, out + 1, out, N);

    // 2) per-edge fused: dot + gate + pair potential + scatter + energy
    //    8 lanes per group, 8 edges per group -> 1 thread per edge
    long long ethreads = ((long long)E + 7) / 8 * 8;
    edge_kernel<<<(int)((ethreads + 255) / 256), 256>>>(y, bond, src, dst,
                                                        Weg, beg, out + 1, out,
                                                        E, 1.0f / (float)N);
}

// round 8
// speedup vs baseline: 2.7823x; 1.0869x over previous
#include <cuda_runtime.h>
#include <math_constants.h>

#define HID   64
#define MAXN  50000

// Per-node precomputed tables, stride 8 floats for float4 alignment.
// srcTab[n*8 + 0..3] = ps (x0·Wsp + bsp), [n*8+4] = gs (x·Wsg + bsg)
// dstTab[n*8 + 0..3] = pd (x0·Wdp),       [n*8+4] = gd (x·Wdg + bdg)
__device__ float g_srcTab[MAXN * 8];
__device__ float g_dstTab[MAXN * 8];

// 8 lanes per node; lane handles elements [sub*4 .. sub*4+3] and [32+sub*4 ..].
// Butterfly transpose-reduce; distributed stores. Also zeroes output accumulators.
__global__ void node_kernel(const float* __restrict__ x,
                            const float* __restrict__ x0,
                            const float* __restrict__ Wsg, const float* __restrict__ bsg,
                            const float* __restrict__ Wdg, const float* __restrict__ bdg,
                            const float* __restrict__ Wsp, const float* __restrict__ bsp,
                            const float* __restrict__ Wdp,
                            float* __restrict__ atom, float* __restrict__ out0,
                            int n)
{
    int t    = blockIdx.x * blockDim.x + threadIdx.x;
    int node = t >> 3;
    int sub  = t & 7;
    if (node >= n) return;

    const size_t base = (size_t)node * HID;
    const int h0 = sub * 4;        // first element of chunk A
    const int h1 = 32 + sub * 4;   // first element of chunk B

    float4 xa  = *(const float4*)(x  + base + h0);
    float4 xb  = *(const float4*)(x  + base + h1);
    float4 x0a = *(const float4*)(x0 + base + h0);
    float4 x0b = *(const float4*)(x0 + base + h1);

    float gs = 0.f, gd = 0.f;
    float v[8];                    // 0..3 = ps partials, 4..7 = pd partials
#pragma unroll
    for (int p = 0; p < 8; p++) v[p] = 0.f;

    const float* xav  = (const float*)&xa;
    const float* xbv  = (const float*)&xb;
    const float* x0av = (const float*)&x0a;
    const float* x0bv = (const float*)&x0b;

#pragma unroll
    for (int k = 0; k < 4; k++) {
        int ha = h0 + k, hb = h1 + k;
        gs += xav[k] * __ldg(Wsg + ha) + xbv[k] * __ldg(Wsg + hb);
        gd += xav[k] * __ldg(Wdg + ha) + xbv[k] * __ldg(Wdg + hb);
        float4 wsa = *(const float4*)(Wsp + ha * 4);
        float4 wsb = *(const float4*)(Wsp + hb * 4);
        float4 wda = *(const float4*)(Wdp + ha * 4);
        float4 wdb = *(const float4*)(Wdp + hb * 4);
        v[0] += x0av[k] * wsa.x + x0bv[k] * wsb.x;
        v[1] += x0av[k] * wsa.y + x0bv[k] * wsb.y;
        v[2] += x0av[k] * wsa.z + x0bv[k] * wsb.z;
        v[3] += x0av[k] * wsa.w + x0bv[k] * wsb.w;
        v[4] += x0av[k] * wda.x + x0bv[k] * wdb.x;
        v[5] += x0av[k] * wda.y + x0bv[k] * wdb.y;
        v[6] += x0av[k] * wda.z + x0bv[k] * wdb.z;
        v[7] += x0av[k] * wda.w + x0bv[k] * wdb.w;
    }

    // transpose-reduce: 7 shuffles; lane sub ends with sum over group of v[sub]
    bool hi4 = (sub & 4) != 0;
    float a0k = hi4 ? v[4] : v[0], a0s = hi4 ? v[0] : v[4];
    float a1k = hi4 ? v[5] : v[1], a1s = hi4 ? v[1] : v[5];
    float a2k = hi4 ? v[6] : v[2], a2s = hi4 ? v[2] : v[6];
    float a3k = hi4 ? v[7] : v[3], a3s = hi4 ? v[3] : v[7];
    a0k += __shfl_xor_sync(0xffffffffu, a0s, 4);
    a1k += __shfl_xor_sync(0xffffffffu, a1s, 4);
    a2k += __shfl_xor_sync(0xffffffffu, a2s, 4);
    a3k += __shfl_xor_sync(0xffffffffu, a3s, 4);
    bool hi2 = (sub & 2) != 0;
    float b0k = hi2 ? a2k : a0k, b0s = hi2 ? a0k : a2k;
    float b1k = hi2 ? a3k : a1k, b1s = hi2 ? a1k : a3k;
    b0k += __shfl_xor_sync(0xffffffffu, b0s, 2);
    b1k += __shfl_xor_sync(0xffffffffu, b1s, 2);
    bool hi1 = (sub & 1) != 0;
    float ck = hi1 ? b1k : b0k, cs = hi1 ? b0k : b1k;
    ck += __shfl_xor_sync(0xffffffffu, cs, 1);

    // plain reduce for the two gate scalars (6 shuffles)
#pragma unroll
    for (int off = 4; off >= 1; off >>= 1) {
        gs += __shfl_xor_sync(0xffffffffu, gs, off);
        gd += __shfl_xor_sync(0xffffffffu, gd, off);
    }

    // distributed stores: lane sub<4 -> srcTab param, sub>=4 -> dstTab param
    if (sub < 4)
        g_srcTab[(size_t)node * 8 + sub] = ck + __ldg(bsp + sub);
    else
        g_dstTab[(size_t)node * 8 + (sub - 4)] = ck;
    if (sub == 0) {
        g_srcTab[(size_t)node * 8 + 4] = gs + __ldg(bsg);
        g_dstTab[(size_t)node * 8 + 4] = gd + __ldg(bdg);
        atom[node] = 0.0f;                 // zero the scatter accumulator
        if (node == 0) *out0 = 0.0f;       // zero the energy accumulator
    }
}

// Persistent grid-stride edge kernel. Each block loops over chunks of 256
// edges (32 groups x 8 edges). Cross-iteration pipeline: the bond lengths
// for chunk i are loaded during iteration i-1, so the y loads of iteration i
// issue immediately — the serial bond->y DRAM chain is paid only once per
// block instead of once per wave. Energy reduction hoisted out of the loop.
__global__ void __launch_bounds__(256, 5)
edge_kernel(const float* __restrict__ y,
            const float* __restrict__ bondlength,
            const int* __restrict__ src,
            const int* __restrict__ dst,
            const float* __restrict__ Weg,
            const float* __restrict__ beg,
            float* __restrict__ atom,
            float* __restrict__ out0,
            int E, float invN)
{
    __shared__ float sWeg[HID];
    __shared__ float sEsum;
    int tid = threadIdx.x;
    if (tid < HID) sWeg[tid] = Weg[tid];
    if (tid == 0)  sEsum = 0.0f;
    __syncthreads();

    const int sub      = tid & 7;
    const int grpInBlk = tid >> 3;             // 0..31
    const float4 wa = *(const float4*)(sWeg + sub * 4);
    const float4 wb = *(const float4*)(sWeg + 32 + sub * 4);
    const float begv = __ldg(beg);

    const int CHUNK = 256;                     // edges per block-iteration
    const int nChunks = (E + CHUNK - 1) / CHUNK;

    float Vacc = 0.0f;
    int chunk = blockIdx.x;

    float r[8];
    if (chunk < nChunks) {
        int e0 = chunk * CHUNK + grpInBlk * 8;
#pragma unroll
        for (int p = 0; p < 8; p++)
            r[p] = (e0 + p < E) ? __ldg(bondlength + e0 + p) : 5.0f;
    }

    for (; chunk < nChunks; chunk += gridDim.x) {
        const int e0 = chunk * CHUNK + grpInBlk * 8;
        const float* ybase = y + (size_t)e0 * HID;

        // 1) y loads gated on already-resident r[] (evict-first stream)
        float d[8];
#pragma unroll
        for (int p = 0; p < 8; p += 2) {
            float da = 0.f, db = 0.f;
            if (r[p] <= 4.0f) {
                const float* row = ybase + (size_t)p * HID;
                float4 a = __ldcs((const float4*)(row + sub * 4));
                float4 b = __ldcs((const float4*)(row + 32 + sub * 4));
                da = a.x*wa.x + a.y*wa.y + a.z*wa.z + a.w*wa.w
                   + b.x*wb.x + b.y*wb.y + b.z*wb.z + b.w*wb.w;
            }
            if (r[p + 1] <= 4.0f) {
                const float* row = ybase + (size_t)(p + 1) * HID;
                float4 a = __ldcs((const float4*)(row + sub * 4));
                float4 b = __ldcs((const float4*)(row + 32 + sub * 4));
                db = a.x*wa.x + a.y*wa.y + a.z*wa.z + a.w*wa.w
                   + b.x*wb.x + b.y*wb.y + b.z*wb.z + b.w*wb.w;
            }
            d[p] = da; d[p + 1] = db;
        }

        // 2) prefetch NEXT chunk's bond lengths straight into r[]
        {
            int nchunk = chunk + gridDim.x;
            if (nchunk < nChunks) {
                int ne0 = nchunk * CHUNK + grpInBlk * 8;
#pragma unroll
                for (int p = 0; p < 8; p++)
                    r[p] = (ne0 + p < E) ? __ldg(bondlength + ne0 + p) : 5.0f;
            }
        }

        // 3) transpose-reduce: 7 shuffles; lane sub holds dot of edge e0+sub
        bool hi4 = (sub & 4) != 0;
        float a0k = hi4 ? d[4] : d[0], a0s = hi4 ? d[0] : d[4];
        float a1k = hi4 ? d[5] : d[1], a1s = hi4 ? d[1] : d[5];
        float a2k = hi4 ? d[6] : d[2], a2s = hi4 ? d[2] : d[6];
        float a3k = hi4 ? d[7] : d[3], a3s = hi4 ? d[3] : d[7];
        a0k += __shfl_xor_sync(0xffffffffu, a0s, 4);
        a1k += __shfl_xor_sync(0xffffffffu, a1s, 4);
        a2k += __shfl_xor_sync(0xffffffffu, a2s, 4);
        a3k += __shfl_xor_sync(0xffffffffu, a3s, 4);
        bool hi2 = (sub & 2) != 0;
        float b0k = hi2 ? a2k : a0k, b0s = hi2 ? a0k : a2k;
        float b1k = hi2 ? a3k : a1k, b1s = hi2 ? a1k : a3k;
        b0k += __shfl_xor_sync(0xffffffffu, b0s, 2);
        b1k += __shfl_xor_sync(0xffffffffu, b1s, 2);
        bool hi1 = (sub & 1) != 0;
        float myd = hi1 ? b1k : b0k, cs = hi1 ? b0k : b1k;
        myd += __shfl_xor_sync(0xffffffffu, cs, 1);

        // 4) tail: lane sub handles edge e0+sub (bond reload = L1 hit)
        int e = e0 + sub;
        if (e < E) {
            float myr = __ldg(bondlength + e);
            if (myr <= 4.0f) {
                int s  = src[e];
                int dn = dst[e];
                float4 ps = *(const float4*)(g_srcTab + (size_t)s * 8);
                float  gs = g_srcTab[(size_t)s * 8 + 4];
                float4 pd = *(const float4*)(g_dstTab + (size_t)dn * 8);
                float  gd = g_dstTab[(size_t)dn * 8 + 4];

                float m  = gs + gd + myd + begv;
                float bo = 1.0f / (1.0f + __expf(-m));

                float p0 = __expf(ps.x + pd.x);
                float p1 = __expf(ps.y + pd.y);
                float p2 = __expf(ps.z + pd.z);
                float p3 = __expf(ps.w + pd.w);

                float frep = p0 * __expf(-p1 * myr);
                float fatt = p2 * __expf(-p3 * myr);

                // cutoff: 1 for r<3.8; 0.5-0.5*sin(pi*(r-3.9)/0.2) in [3.8,4.0]
                float c = 1.0f;
                if (myr >= 3.8f)
                    c = 0.5f - 0.5f * __sinf(CUDART_PI_F * (myr - 3.9f) * 5.0f);

                float V = c * (frep - bo * fatt);
                atomicAdd(atom + dn, V);
                Vacc += V;
            }
        }
    }

    // once per block: energy accumulation
#pragma unroll
    for (int off = 16; off >= 1; off >>= 1)
        Vacc += __shfl_xor_sync(0xffffffffu, Vacc, off);
    if ((tid & 31) == 0 && Vacc != 0.0f)
        atomicAdd(&sEsum, Vacc);
    __syncthreads();
    if (tid == 0)
        atomicAdd(out0, sEsum * invN);
}

extern "C" void kernel_launch(void* const* d_in, const int* in_sizes, int n_in,
                              void* d_out, int out_size)
{
    const float* x    = (const float*)d_in[0];
    const float* x0   = (const float*)d_in[1];
    const float* y    = (const float*)d_in[2];
    const float* bond = (const float*)d_in[3];
    const int*   src  = (const int*)d_in[4];
    const int*   dst  = (const int*)d_in[5];
    const float* Wsg  = (const float*)d_in[6];
    const float* bsg  = (const float*)d_in[7];
    const float* Wdg  = (const float*)d_in[8];
    const float* bdg  = (const float*)d_in[9];
    const float* Weg  = (const float*)d_in[10];
    const float* beg  = (const float*)d_in[11];
    const float* Wsp  = (const float*)d_in[12];
    const float* bsp  = (const float*)d_in[13];
    const float* Wdp  = (const float*)d_in[14];

    const int N = in_sizes[0] / HID;   // 50000
    const int E = in_sizes[3];         // 1600000

    float* out = (float*)d_out;        // out[0] = energy, out[1..N] = atomwise

    // 1) per-node gate/param precompute + zero the output accumulators
    node_kernel<<<(N * 8 + 255) / 256, 256>>>(x, x0, Wsg, bsg, Wdg, bdg,
                                              Wsp, bsp, Wdp, out + 1, out, N);

    // 2) persistent fused edge kernel: 148 SMs x 5 blocks
    int nChunks = (E + 255) / 256;
    int grid = 148 * 5;
    if (grid > nChunks) grid = nChunks;
    edge_kernel<<<grid, 256>>>(y, bond, src, dst, Weg, beg, out + 1, out,
                               E, 1.0f / (float)N);
}